// round 3
// baseline (speedup 1.0000x reference)
#include <cuda_runtime.h>
#include <math.h>

#define HD 1024
#define NB 64   // spectral blocks

// ---- scratch: one big device array + offsets (floats) ----
#define OFF_XB  0UL
#define OFF_ANT 33554432UL
#define OFF_WBT (OFF_ANT+1048576UL)
#define OFF_WCT (OFF_WBT+1048576UL)
#define OFF_P   (OFF_WCT+1048576UL)
#define OFF_Q   (OFF_P  +1048576UL)
#define OFF_H0  (OFF_Q  +1048576UL)
#define OFF_H1  (OFF_H0 +2097152UL)
#define OFF_C   (OFF_H1 +2097152UL)
#define SCR_TOT (OFF_C  +2097152UL)
__device__ float g_scr[SCR_TOT];

__device__ float sp_partial[NB*HD];
__device__ float sp_u[HD], sp_v[HD], sp_w[HD];
__device__ float sp_norm;
__device__ float d_rsigma[3];
__device__ unsigned bar_cnt = 0, bar_gen = 0;

__device__ __forceinline__ void gridbar() {
    __syncthreads(); __threadfence();
    if (threadIdx.x == 0) {
        unsigned g = atomicAdd(&bar_gen, 0u);
        if (atomicAdd(&bar_cnt, 1u) == NB - 1u) {
            bar_cnt = 0u; __threadfence(); atomicExch(&bar_gen, g + 1u);
        } else while (atomicAdd(&bar_gen, 0u) == g) __nanosleep(64);
    }
    __syncthreads();
}

__global__ void __launch_bounds__(256) spectral_kernel(const float* __restrict__ WA,
    const float* __restrict__ WB, const float* __restrict__ WC) {
    __shared__ float red[256];
    const int tid = threadIdx.x, bid = blockIdx.x, gtid = bid*256 + tid;
    const float* Ws[3] = {WA, WB, WC};
    for (int m = 0; m < 3; m++) {
        const float* W = Ws[m];
        if (gtid < HD) sp_u[gtid] = 0.03125f;
        gridbar();
        for (int it = 0; it <= 10; it++) {
            { // v_raw = W^T u  (block owns 16 rows of i)
                const int i0 = bid*16;
                float a0=0,a1=0,a2=0,a3=0;
                for (int i = i0; i < i0+16; i++) {
                    float ui = __ldcg(&sp_u[i]);
                    const float* Wr = W + (size_t)i*HD;
                    a0 += Wr[tid]*ui; a1 += Wr[tid+256]*ui;
                    a2 += Wr[tid+512]*ui; a3 += Wr[tid+768]*ui;
                }
                sp_partial[bid*HD+tid]=a0; sp_partial[bid*HD+tid+256]=a1;
                sp_partial[bid*HD+tid+512]=a2; sp_partial[bid*HD+tid+768]=a3;
            }
            gridbar();
            if (gtid < HD) { float s=0; for (int b=0;b<NB;b++) s += __ldcg(&sp_partial[b*HD+gtid]); sp_v[gtid]=s; }
            gridbar();
            if (bid == 0) {
                float s=0;
                #pragma unroll
                for (int q=0;q<4;q++){ float x=__ldcg(&sp_v[tid*4+q]); s+=x*x; }
                red[tid]=s; __syncthreads();
                for (int st=128;st>0;st>>=1){ if(tid<st) red[tid]+=red[tid+st]; __syncthreads(); }
                if (tid==0) sp_norm = sqrtf(red[0]) + 1e-12f;
            }
            gridbar();
            if (gtid < HD) sp_v[gtid] = __ldcg(&sp_v[gtid]) / __ldcg(&sp_norm);
            gridbar();
            if (it == 10) break;
            { // u_raw = W v  (warp per row)
                const int warp = gtid>>5, lane = gtid&31;
                for (int i = warp; i < HD; i += (NB*256)/32) {
                    const float* Wr = W + (size_t)i*HD;
                    float s=0;
                    for (int j=lane;j<HD;j+=32) s += Wr[j]*__ldcg(&sp_v[j]);
                    #pragma unroll
                    for (int o=16;o;o>>=1) s += __shfl_xor_sync(0xffffffffu,s,o);
                    if (lane==0) sp_u[i]=s;
                }
            }
            gridbar();
            if (bid == 0) {
                float s=0;
                #pragma unroll
                for (int q=0;q<4;q++){ float x=__ldcg(&sp_u[tid*4+q]); s+=x*x; }
                red[tid]=s; __syncthreads();
                for (int st=128;st>0;st>>=1){ if(tid<st) red[tid]+=red[tid+st]; __syncthreads(); }
                if (tid==0) sp_norm = sqrtf(red[0]) + 1e-12f;
            }
            gridbar();
            if (gtid < HD) sp_u[gtid] = __ldcg(&sp_u[gtid]) / __ldcg(&sp_norm);
            gridbar();
        }
        { // w = W v ; sigma = u . w
            const int warp = gtid>>5, lane = gtid&31;
            for (int i = warp; i < HD; i += (NB*256)/32) {
                const float* Wr = W + (size_t)i*HD;
                float s=0;
                for (int j=lane;j<HD;j+=32) s += Wr[j]*__ldcg(&sp_v[j]);
                #pragma unroll
                for (int o=16;o;o>>=1) s += __shfl_xor_sync(0xffffffffu,s,o);
                if (lane==0) sp_w[i]=s;
            }
        }
        gridbar();
        if (bid == 0) {
            float s=0;
            #pragma unroll
            for (int q=0;q<4;q++) s += __ldcg(&sp_u[tid*4+q])*__ldcg(&sp_w[tid*4+q]);
            red[tid]=s; __syncthreads();
            for (int st=128;st>0;st>>=1){ if(tid<st) red[tid]+=red[tid+st]; __syncthreads(); }
            if (tid==0) d_rsigma[m] = 1.0f/red[0];
        }
        gridbar();
    }
}

// WT[i][h] = W[h][i] * rsigma[sidx]
__global__ void transpose_scale(const float* __restrict__ W, float* __restrict__ WT, int sidx) {
    __shared__ float tile[32][33];
    const float s = d_rsigma[sidx];
    const int x = blockIdx.x*32 + threadIdx.x, y0 = blockIdx.y*32;
    #pragma unroll
    for (int i = threadIdx.y; i < 32; i += 8)
        tile[i][threadIdx.x] = W[(size_t)(y0+i)*HD + x];
    __syncthreads();
    const int ox = y0 + threadIdx.x, oy0 = blockIdx.x*32;
    #pragma unroll
    for (int i = threadIdx.y; i < 32; i += 8)
        WT[(size_t)(oy0+i)*HD + ox] = tile[threadIdx.x][i] * s;
}

// SGEMM NN: C = A[M,1024]*B[1024,1024] (+Add). 128x128x8 tile, 256 thr, 8x8/thr.
// mode 0: C[r]=v. mode 1 (xb): write C at scan-layout row. mode 2: C[r]=v AND out2 at hs row.
__global__ void __launch_bounds__(256) sgemm(const float* __restrict__ A,
    const float* __restrict__ B, float* __restrict__ C, const float* __restrict__ Add,
    int mode, int jparam, float* __restrict__ out2) {
    __shared__ float As[8][132];
    __shared__ float Bs[8][128];
    const int tid = threadIdx.x, ty = tid>>4, tx = tid&15;
    const int m0 = blockIdx.y*128, n0 = blockIdx.x*128;
    float acc[8][8];
    #pragma unroll
    for (int i=0;i<8;i++)
        #pragma unroll
        for (int j=0;j<8;j++) acc[i][j]=0.f;
    const int arow = tid>>1, acol = (tid&1)*4;
    const int brow = tid>>5, bcol = (tid&31)*4;
    for (int k0 = 0; k0 < 1024; k0 += 8) {
        float4 av = *(const float4*)(A + (size_t)(m0+arow)*1024 + k0 + acol);
        As[acol+0][arow]=av.x; As[acol+1][arow]=av.y; As[acol+2][arow]=av.z; As[acol+3][arow]=av.w;
        *(float4*)&Bs[brow][bcol] = *(const float4*)(B + (size_t)(k0+brow)*1024 + n0 + bcol);
        __syncthreads();
        #pragma unroll
        for (int kk=0;kk<8;kk++) {
            float a[8], b[8];
            *(float4*)&a[0] = *(const float4*)&As[kk][ty*4];
            *(float4*)&a[4] = *(const float4*)&As[kk][64+ty*4];
            *(float4*)&b[0] = *(const float4*)&Bs[kk][tx*4];
            *(float4*)&b[4] = *(const float4*)&Bs[kk][64+tx*4];
            #pragma unroll
            for (int i=0;i<8;i++)
                #pragma unroll
                for (int j=0;j<8;j++) acc[i][j] = fmaf(a[i], b[j], acc[i][j]);
        }
        __syncthreads();
    }
    #pragma unroll
    for (int gi=0;gi<2;gi++)
    #pragma unroll
    for (int ii=0;ii<4;ii++) {
        const int r = m0 + gi*64 + ty*4 + ii;
        #pragma unroll
        for (int gj=0;gj<2;gj++) {
            const int c = n0 + gj*64 + tx*4;
            float4 v;
            v.x=acc[gi*4+ii][gj*4+0]; v.y=acc[gi*4+ii][gj*4+1];
            v.z=acc[gi*4+ii][gj*4+2]; v.w=acc[gi*4+ii][gj*4+3];
            if (Add) {
                float4 ad = *(const float4*)(Add + (size_t)r*1024 + c);
                v.x+=ad.x; v.y+=ad.y; v.z+=ad.z; v.w+=ad.w;
            }
            if (mode == 1) {
                int b_ = r>>10, t = r&1023, k = t>>4, j = t&15;
                size_t orow = (size_t)((((j<<6)|k)<<5)|b_);
                *(float4*)(C + orow*1024 + c) = v;
            } else {
                *(float4*)(C + (size_t)r*1024 + c) = v;
                if (mode == 2) {
                    int k = r>>5, b_ = r&31;
                    size_t orow = (size_t)b_*1024 + k*16 + jparam;
                    *(float4*)(out2 + orow*1024 + c) = v;
                }
            }
        }
    }
}

// small GEMM: C[32,1024] = A[32,1024]*Q[1024,1024] + Add. 64 blocks x 16 cols.
__global__ void __launch_bounds__(256) smallgemm(const float* __restrict__ A,
    const float* __restrict__ Q, float* __restrict__ C, const float* __restrict__ Add) {
    __shared__ float As[32*129];
    const int tid = threadIdx.x;
    const int row = tid & 31;
    const int c0 = blockIdx.x*16 + (tid>>5)*2;
    float acc0 = 0.f, acc1 = 0.f;
    for (int k0 = 0; k0 < 1024; k0 += 128) {
        #pragma unroll
        for (int q = 0; q < 16; q++) {
            int l = q*256 + tid, r = l>>7, cc = l&127;
            As[r*129 + cc] = A[(size_t)r*1024 + k0 + cc];
        }
        __syncthreads();
        #pragma unroll 4
        for (int kk = 0; kk < 128; kk++) {
            float a = As[row*129 + kk];
            float2 qv = *(const float2*)(Q + (size_t)(k0+kk)*1024 + c0);
            acc0 = fmaf(a, qv.x, acc0); acc1 = fmaf(a, qv.y, acc1);
        }
        __syncthreads();
    }
    C[(size_t)row*1024 + c0]     = acc0 + Add[(size_t)row*1024 + c0];
    C[(size_t)row*1024 + c0 + 1] = acc1 + Add[(size_t)row*1024 + c0 + 1];
}

__global__ void zero32k(float* p) {
    int i = blockIdx.x*256 + threadIdx.x;
    if (i < 32768) p[i] = 0.f;
}

extern "C" void kernel_launch(void* const* d_in, const int* in_sizes, int n_in,
                              void* d_out, int out_size) {
    const float* x  = (const float*)d_in[0];
    const float* WA = (const float*)d_in[1];
    const float* WB = (const float*)d_in[2];
    const float* WC = (const float*)d_in[3];
    float* ys = (float*)d_out;
    float* hs = ys + 33554432UL;

    float* scr = nullptr;
    cudaGetSymbolAddress((void**)&scr, g_scr);
    float* xb  = scr + OFF_XB;
    float* ANT = scr + OFF_ANT;
    float* WBT = scr + OFF_WBT;
    float* WCT = scr + OFF_WCT;
    float* P   = scr + OFF_P;
    float* Q   = scr + OFF_Q;
    float* H0  = scr + OFF_H0;
    float* H1  = scr + OFF_H1;
    float* Cb  = scr + OFF_C;

    spectral_kernel<<<NB, 256>>>(WA, WB, WC);

    dim3 tb(32, 8), tg(32, 32);
    transpose_scale<<<tg, tb>>>(WA, ANT, 0);
    transpose_scale<<<tg, tb>>>(WB, WBT, 1);
    transpose_scale<<<tg, tb>>>(WC, WCT, 2);

    // xb = X * WBT, written in scan layout
    sgemm<<<dim3(8, 256), 256>>>(x, WBT, xb, nullptr, 1, 0, nullptr);

    // Q = ANT^16 via 4 squarings
    sgemm<<<dim3(8, 8), 256>>>(ANT, ANT, P, nullptr, 0, 0, nullptr);
    sgemm<<<dim3(8, 8), 256>>>(P, P, Q, nullptr, 0, 0, nullptr);
    sgemm<<<dim3(8, 8), 256>>>(Q, Q, P, nullptr, 0, 0, nullptr);
    sgemm<<<dim3(8, 8), 256>>>(P, P, Q, nullptr, 0, 0, nullptr);

    // pass 1: local scans (zero init). S_0 = xb slice 0. S_j = S_{j-1}*ANT + xb_j
    const float* prev = xb;
    for (int j = 1; j < 16; j++) {
        float* dst = (j & 1) ? H1 : H0;
        sgemm<<<dim3(8, 16), 256>>>(prev, ANT, dst, xb + (size_t)j*2097152UL, 0, 0, nullptr);
        prev = dst;
    }
    // L_last = H1 (j=15)

    // pass 2: carries c_k = c_{k-1}*Q + L_last(k-1), c_0 = 0
    zero32k<<<128, 256>>>(Cb);
    for (int k = 1; k < 64; k++)
        smallgemm<<<64, 256>>>(Cb + (size_t)(k-1)*32768UL, Q,
                               Cb + (size_t)k*32768UL, H1 + (size_t)(k-1)*32768UL);

    // pass 3: full scan with true inits, scatter into hs
    prev = Cb;
    for (int j = 0; j < 16; j++) {
        float* dst = (j & 1) ? H1 : H0;
        sgemm<<<dim3(8, 16), 256>>>(prev, ANT, dst, xb + (size_t)j*2097152UL, 2, j, hs);
        prev = dst;
    }

    // ys = hs * WCT
    sgemm<<<dim3(8, 256), 256>>>(hs, WCT, ys, nullptr, 0, 0, nullptr);
    (void)in_sizes; (void)n_in; (void)out_size;
}

// round 4
// speedup vs baseline: 1.0024x; 1.0024x over previous
#include <cuda_runtime.h>
#include <math.h>

#define HD 1024
#define NB 64   // spectral blocks

// ---- scratch: one big device array + offsets (floats) ----
#define OFF_XB  0UL
#define OFF_ANT 33554432UL
#define OFF_WBT (OFF_ANT+1048576UL)
#define OFF_WCT (OFF_WBT+1048576UL)
#define OFF_P   (OFF_WCT+1048576UL)
#define OFF_Q   (OFF_P  +1048576UL)
#define OFF_H0  (OFF_Q  +1048576UL)
#define OFF_H1  (OFF_H0 +2097152UL)
#define OFF_C   (OFF_H1 +2097152UL)
#define SCR_TOT (OFF_C  +2097152UL)
__device__ float g_scr[SCR_TOT];

__device__ float sp_partial[NB*HD];
__device__ float sp_u[HD], sp_v[HD], sp_w[HD];
__device__ float sp_norm;
__device__ float d_rsigma[3];
__device__ unsigned bar_cnt = 0, bar_gen = 0;

__device__ __forceinline__ void gridbar() {
    __syncthreads(); __threadfence();
    if (threadIdx.x == 0) {
        unsigned g = atomicAdd(&bar_gen, 0u);
        if (atomicAdd(&bar_cnt, 1u) == NB - 1u) {
            bar_cnt = 0u; __threadfence(); atomicExch(&bar_gen, g + 1u);
        } else while (atomicAdd(&bar_gen, 0u) == g) __nanosleep(64);
    }
    __syncthreads();
}

__global__ void __launch_bounds__(256) spectral_kernel(const float* __restrict__ WA,
    const float* __restrict__ WB, const float* __restrict__ WC) {
    __shared__ float red[256];
    const int tid = threadIdx.x, bid = blockIdx.x, gtid = bid*256 + tid;
    const float* Ws[3] = {WA, WB, WC};
    for (int m = 0; m < 3; m++) {
        const float* W = Ws[m];
        if (gtid < HD) sp_u[gtid] = 0.03125f;
        gridbar();
        for (int it = 0; it <= 10; it++) {
            { // v_raw = W^T u  (block owns 16 rows of i)
                const int i0 = bid*16;
                float a0=0,a1=0,a2=0,a3=0;
                for (int i = i0; i < i0+16; i++) {
                    float ui = __ldcg(&sp_u[i]);
                    const float* Wr = W + (size_t)i*HD;
                    a0 += Wr[tid]*ui; a1 += Wr[tid+256]*ui;
                    a2 += Wr[tid+512]*ui; a3 += Wr[tid+768]*ui;
                }
                sp_partial[bid*HD+tid]=a0; sp_partial[bid*HD+tid+256]=a1;
                sp_partial[bid*HD+tid+512]=a2; sp_partial[bid*HD+tid+768]=a3;
            }
            gridbar();
            if (gtid < HD) { float s=0; for (int b=0;b<NB;b++) s += __ldcg(&sp_partial[b*HD+gtid]); sp_v[gtid]=s; }
            gridbar();
            if (bid == 0) {
                float s=0;
                #pragma unroll
                for (int q=0;q<4;q++){ float x=__ldcg(&sp_v[tid*4+q]); s+=x*x; }
                red[tid]=s; __syncthreads();
                for (int st=128;st>0;st>>=1){ if(tid<st) red[tid]+=red[tid+st]; __syncthreads(); }
                if (tid==0) sp_norm = sqrtf(red[0]) + 1e-12f;
            }
            gridbar();
            if (gtid < HD) sp_v[gtid] = __ldcg(&sp_v[gtid]) / __ldcg(&sp_norm);
            gridbar();
            if (it == 10) break;
            { // u_raw = W v  (warp per row)
                const int warp = gtid>>5, lane = gtid&31;
                for (int i = warp; i < HD; i += (NB*256)/32) {
                    const float* Wr = W + (size_t)i*HD;
                    float s=0;
                    for (int j=lane;j<HD;j+=32) s += Wr[j]*__ldcg(&sp_v[j]);
                    #pragma unroll
                    for (int o=16;o;o>>=1) s += __shfl_xor_sync(0xffffffffu,s,o);
                    if (lane==0) sp_u[i]=s;
                }
            }
            gridbar();
            if (bid == 0) {
                float s=0;
                #pragma unroll
                for (int q=0;q<4;q++){ float x=__ldcg(&sp_u[tid*4+q]); s+=x*x; }
                red[tid]=s; __syncthreads();
                for (int st=128;st>0;st>>=1){ if(tid<st) red[tid]+=red[tid+st]; __syncthreads(); }
                if (tid==0) sp_norm = sqrtf(red[0]) + 1e-12f;
            }
            gridbar();
            if (gtid < HD) sp_u[gtid] = __ldcg(&sp_u[gtid]) / __ldcg(&sp_norm);
            gridbar();
        }
        { // w = W v ; sigma = u . w
            const int warp = gtid>>5, lane = gtid&31;
            for (int i = warp; i < HD; i += (NB*256)/32) {
                const float* Wr = W + (size_t)i*HD;
                float s=0;
                for (int j=lane;j<HD;j+=32) s += Wr[j]*__ldcg(&sp_v[j]);
                #pragma unroll
                for (int o=16;o;o>>=1) s += __shfl_xor_sync(0xffffffffu,s,o);
                if (lane==0) sp_w[i]=s;
            }
        }
        gridbar();
        if (bid == 0) {
            float s=0;
            #pragma unroll
            for (int q=0;q<4;q++) s += __ldcg(&sp_u[tid*4+q])*__ldcg(&sp_w[tid*4+q]);
            red[tid]=s; __syncthreads();
            for (int st=128;st>0;st>>=1){ if(tid<st) red[tid]+=red[tid+st]; __syncthreads(); }
            if (tid==0) d_rsigma[m] = 1.0f/red[0];
        }
        gridbar();
    }
}

// WT[i][h] = W[h][i] * rsigma[sidx]
__global__ void transpose_scale(const float* __restrict__ W, float* __restrict__ WT, int sidx) {
    __shared__ float tile[32][33];
    const float s = d_rsigma[sidx];
    const int x = blockIdx.x*32 + threadIdx.x, y0 = blockIdx.y*32;
    #pragma unroll
    for (int i = threadIdx.y; i < 32; i += 8)
        tile[i][threadIdx.x] = W[(size_t)(y0+i)*HD + x];
    __syncthreads();
    const int ox = y0 + threadIdx.x, oy0 = blockIdx.x*32;
    #pragma unroll
    for (int i = threadIdx.y; i < 32; i += 8)
        WT[(size_t)(oy0+i)*HD + ox] = tile[threadIdx.x][i] * s;
}

// SGEMM NN: C = A[M,1024]*B[1024,1024] (+Add). 128x128x8 tile, 256 thr, 8x8/thr.
// mode 0: C[r]=v. mode 1 (xb): write C at scan-layout row. mode 2: C[r]=v AND out2 at hs row.
__global__ void __launch_bounds__(256) sgemm(const float* __restrict__ A,
    const float* __restrict__ B, float* __restrict__ C, const float* __restrict__ Add,
    int mode, int jparam, float* __restrict__ out2) {
    __shared__ float As[8][132];
    __shared__ float Bs[8][128];
    const int tid = threadIdx.x, ty = tid>>4, tx = tid&15;
    const int m0 = blockIdx.y*128, n0 = blockIdx.x*128;
    float acc[8][8];
    #pragma unroll
    for (int i=0;i<8;i++)
        #pragma unroll
        for (int j=0;j<8;j++) acc[i][j]=0.f;
    const int arow = tid>>1, acol = (tid&1)*4;
    const int brow = tid>>5, bcol = (tid&31)*4;
    for (int k0 = 0; k0 < 1024; k0 += 8) {
        float4 av = *(const float4*)(A + (size_t)(m0+arow)*1024 + k0 + acol);
        As[acol+0][arow]=av.x; As[acol+1][arow]=av.y; As[acol+2][arow]=av.z; As[acol+3][arow]=av.w;
        *(float4*)&Bs[brow][bcol] = *(const float4*)(B + (size_t)(k0+brow)*1024 + n0 + bcol);
        __syncthreads();
        #pragma unroll
        for (int kk=0;kk<8;kk++) {
            float a[8], b[8];
            *(float4*)&a[0] = *(const float4*)&As[kk][ty*4];
            *(float4*)&a[4] = *(const float4*)&As[kk][64+ty*4];
            *(float4*)&b[0] = *(const float4*)&Bs[kk][tx*4];
            *(float4*)&b[4] = *(const float4*)&Bs[kk][64+tx*4];
            #pragma unroll
            for (int i=0;i<8;i++)
                #pragma unroll
                for (int j=0;j<8;j++) acc[i][j] = fmaf(a[i], b[j], acc[i][j]);
        }
        __syncthreads();
    }
    #pragma unroll
    for (int gi=0;gi<2;gi++)
    #pragma unroll
    for (int ii=0;ii<4;ii++) {
        const int r = m0 + gi*64 + ty*4 + ii;
        #pragma unroll
        for (int gj=0;gj<2;gj++) {
            const int c = n0 + gj*64 + tx*4;
            float4 v;
            v.x=acc[gi*4+ii][gj*4+0]; v.y=acc[gi*4+ii][gj*4+1];
            v.z=acc[gi*4+ii][gj*4+2]; v.w=acc[gi*4+ii][gj*4+3];
            if (Add) {
                float4 ad = *(const float4*)(Add + (size_t)r*1024 + c);
                v.x+=ad.x; v.y+=ad.y; v.z+=ad.z; v.w+=ad.w;
            }
            if (mode == 1) {
                int b_ = r>>10, t = r&1023, k = t>>4, j = t&15;
                size_t orow = (size_t)((((j<<6)|k)<<5)|b_);
                *(float4*)(C + orow*1024 + c) = v;
            } else {
                *(float4*)(C + (size_t)r*1024 + c) = v;
                if (mode == 2) {
                    int k = r>>5, b_ = r&31;
                    size_t orow = (size_t)b_*1024 + k*16 + jparam;
                    *(float4*)(out2 + orow*1024 + c) = v;
                }
            }
        }
    }
}

// small GEMM: C[32,1024] = A[32,1024]*Q[1024,1024] + Add. 64 blocks x 16 cols.
__global__ void __launch_bounds__(256) smallgemm(const float* __restrict__ A,
    const float* __restrict__ Q, float* __restrict__ C, const float* __restrict__ Add) {
    __shared__ float As[32*129];
    const int tid = threadIdx.x;
    const int row = tid & 31;
    const int c0 = blockIdx.x*16 + (tid>>5)*2;
    float acc0 = 0.f, acc1 = 0.f;
    for (int k0 = 0; k0 < 1024; k0 += 128) {
        #pragma unroll
        for (int q = 0; q < 16; q++) {
            int l = q*256 + tid, r = l>>7, cc = l&127;
            As[r*129 + cc] = A[(size_t)r*1024 + k0 + cc];
        }
        __syncthreads();
        #pragma unroll 4
        for (int kk = 0; kk < 128; kk++) {
            float a = As[row*129 + kk];
            float2 qv = *(const float2*)(Q + (size_t)(k0+kk)*1024 + c0);
            acc0 = fmaf(a, qv.x, acc0); acc1 = fmaf(a, qv.y, acc1);
        }
        __syncthreads();
    }
    C[(size_t)row*1024 + c0]     = acc0 + Add[(size_t)row*1024 + c0];
    C[(size_t)row*1024 + c0 + 1] = acc1 + Add[(size_t)row*1024 + c0 + 1];
}

__global__ void zero32k(float* p) {
    int i = blockIdx.x*256 + threadIdx.x;
    if (i < 32768) p[i] = 0.f;
}

extern "C" void kernel_launch(void* const* d_in, const int* in_sizes, int n_in,
                              void* d_out, int out_size) {
    const float* x  = (const float*)d_in[0];
    const float* WA = (const float*)d_in[1];
    const float* WB = (const float*)d_in[2];
    const float* WC = (const float*)d_in[3];
    float* ys = (float*)d_out;
    float* hs = ys + 33554432UL;

    float* scr = nullptr;
    cudaGetSymbolAddress((void**)&scr, g_scr);
    float* xb  = scr + OFF_XB;
    float* ANT = scr + OFF_ANT;
    float* WBT = scr + OFF_WBT;
    float* WCT = scr + OFF_WCT;
    float* P   = scr + OFF_P;
    float* Q   = scr + OFF_Q;
    float* H0  = scr + OFF_H0;
    float* H1  = scr + OFF_H1;
    float* Cb  = scr + OFF_C;

    spectral_kernel<<<NB, 256>>>(WA, WB, WC);

    dim3 tb(32, 8), tg(32, 32);
    transpose_scale<<<tg, tb>>>(WA, ANT, 0);
    transpose_scale<<<tg, tb>>>(WB, WBT, 1);
    transpose_scale<<<tg, tb>>>(WC, WCT, 2);

    // xb = X * WBT, written in scan layout
    sgemm<<<dim3(8, 256), 256>>>(x, WBT, xb, nullptr, 1, 0, nullptr);

    // Q = ANT^16 via 4 squarings
    sgemm<<<dim3(8, 8), 256>>>(ANT, ANT, P, nullptr, 0, 0, nullptr);
    sgemm<<<dim3(8, 8), 256>>>(P, P, Q, nullptr, 0, 0, nullptr);
    sgemm<<<dim3(8, 8), 256>>>(Q, Q, P, nullptr, 0, 0, nullptr);
    sgemm<<<dim3(8, 8), 256>>>(P, P, Q, nullptr, 0, 0, nullptr);

    // pass 1: local scans (zero init). S_0 = xb slice 0. S_j = S_{j-1}*ANT + xb_j
    const float* prev = xb;
    for (int j = 1; j < 16; j++) {
        float* dst = (j & 1) ? H1 : H0;
        sgemm<<<dim3(8, 16), 256>>>(prev, ANT, dst, xb + (size_t)j*2097152UL, 0, 0, nullptr);
        prev = dst;
    }
    // L_last = H1 (j=15)

    // pass 2: carries c_k = c_{k-1}*Q + L_last(k-1), c_0 = 0
    zero32k<<<128, 256>>>(Cb);
    for (int k = 1; k < 64; k++)
        smallgemm<<<64, 256>>>(Cb + (size_t)(k-1)*32768UL, Q,
                               Cb + (size_t)k*32768UL, H1 + (size_t)(k-1)*32768UL);

    // pass 3: full scan with true inits, scatter into hs
    prev = Cb;
    for (int j = 0; j < 16; j++) {
        float* dst = (j & 1) ? H1 : H0;
        sgemm<<<dim3(8, 16), 256>>>(prev, ANT, dst, xb + (size_t)j*2097152UL, 2, j, hs);
        prev = dst;
    }

    // ys = hs * WCT
    sgemm<<<dim3(8, 256), 256>>>(hs, WCT, ys, nullptr, 0, 0, nullptr);
    (void)in_sizes; (void)n_in; (void)out_size;
}

// round 6
// speedup vs baseline: 1.2929x; 1.2899x over previous
#include <cuda_runtime.h>
#include <cuda_bf16.h>
#include <cstdint>
#include <math.h>
#define HD 1024
#define NBS 64
#define F_XB 0UL
#define F_ANT (F_XB+33554432UL)
#define F_P1 (F_ANT+1048576UL)
#define F_P1T (F_P1+1048576UL)
#define F_P2 (F_P1T+1048576UL)
#define F_P2T (F_P2+1048576UL)
#define F_H0 (F_P2T+1048576UL)
#define F_H1 (F_H0+2097152UL)
#define F_CB (F_H1+2097152UL)
#define F_TOT (F_CB+2097152UL)
__device__ float g_f[F_TOT];
__device__ float sp_partial[NBS*HD];
__device__ float sp_u[HD], sp_v[HD], sp_w[HD];
__device__ float sp_norm;
__device__ float d_rsigma[3];
__device__ unsigned bar_cnt = 0, bar_gen = 0;

__device__ __forceinline__ void gridbar() {
    __syncthreads(); __threadfence();
    if (threadIdx.x == 0) {
        unsigned g = atomicAdd(&bar_gen, 0u);
        if (atomicAdd(&bar_cnt, 1u) == NBS - 1u) {
            bar_cnt = 0u; __threadfence(); atomicExch(&bar_gen, g + 1u);
        } else while (atomicAdd(&bar_gen, 0u) == g) __nanosleep(64);
    }
    __syncthreads();
}

__global__ void __launch_bounds__(256) spectral_kernel(const float* __restrict__ WA,
    const float* __restrict__ WB, const float* __restrict__ WC) {
    __shared__ float red[256];
    const int tid = threadIdx.x, bid = blockIdx.x, gtid = bid*256 + tid;
    const float* Ws[3] = {WA, WB, WC};
    for (int m = 0; m < 3; m++) {
        const float* W = Ws[m];
        if (gtid < HD) sp_u[gtid] = 0.03125f;
        gridbar();
        for (int it = 0; it <= 10; it++) {
            const int i0 = bid*16;
            float a0=0,a1=0,a2=0,a3=0;
            for (int i = i0; i < i0+16; i++) {
                float ui = __ldcg(&sp_u[i]);
                const float* Wr = W + (size_t)i*HD;
                a0 += Wr[tid]*ui; a1 += Wr[tid+256]*ui;
                a2 += Wr[tid+512]*ui; a3 += Wr[tid+768]*ui;
            }
            sp_partial[bid*HD+tid]=a0; sp_partial[bid*HD+tid+256]=a1;
            sp_partial[bid*HD+tid+512]=a2; sp_partial[bid*HD+tid+768]=a3;
            gridbar();
            if (gtid < HD) { float s=0; for (int b=0;b<NBS;b++) s += __ldcg(&sp_partial[b*HD+gtid]); sp_v[gtid]=s; }
            gridbar();
            if (bid == 0) {
                float s=0;
                #pragma unroll
                for (int q=0;q<4;q++){ float x=__ldcg(&sp_v[tid*4+q]); s+=x*x; }
                red[tid]=s; __syncthreads();
                for (int st=128;st>0;st>>=1){ if(tid<st) red[tid]+=red[tid+st]; __syncthreads(); }
                if (tid==0) sp_norm = sqrtf(red[0]) + 1e-12f;
            }
            gridbar();
            if (gtid < HD) sp_v[gtid] = __ldcg(&sp_v[gtid]) / __ldcg(&sp_norm);
            gridbar();
            if (it == 10) break;
            { const int warp = gtid>>5, lane = gtid&31;
              for (int i = warp; i < HD; i += (NBS*256)/32) {
                const float* Wr = W + (size_t)i*HD;
                float s=0;
                for (int j=lane;j<HD;j+=32) s += Wr[j]*__ldcg(&sp_v[j]);
                #pragma unroll
                for (int o=16;o;o>>=1) s += __shfl_xor_sync(0xffffffffu,s,o);
                if (lane==0) sp_u[i]=s;
              } }
            gridbar();
            if (bid == 0) {
                float s=0;
                #pragma unroll
                for (int q=0;q<4;q++){ float x=__ldcg(&sp_u[tid*4+q]); s+=x*x; }
                red[tid]=s; __syncthreads();
                for (int st=128;st>0;st>>=1){ if(tid<st) red[tid]+=red[tid+st]; __syncthreads(); }
                if (tid==0) sp_norm = sqrtf(red[0]) + 1e-12f;
            }
            gridbar();
            if (gtid < HD) sp_u[gtid] = __ldcg(&sp_u[gtid]) / __ldcg(&sp_norm);
            gridbar();
        }
        { const int warp = gtid>>5, lane = gtid&31;
          for (int i = warp; i < HD; i += (NBS*256)/32) {
            const float* Wr = W + (size_t)i*HD;
            float s=0;
            for (int j=lane;j<HD;j+=32) s += Wr[j]*__ldcg(&sp_v[j]);
            #pragma unroll
            for (int o=16;o;o>>=1) s += __shfl_xor_sync(0xffffffffu,s,o);
            if (lane==0) sp_w[i]=s;
          } }
        gridbar();
        if (bid == 0) {
            float s=0;
            #pragma unroll
            for (int q=0;q<4;q++) s += __ldcg(&sp_u[tid*4+q])*__ldcg(&sp_w[tid*4+q]);
            red[tid]=s; __syncthreads();
            for (int st=128;st>0;st>>=1){ if(tid<st) red[tid]+=red[tid+st]; __syncthreads(); }
            if (tid==0) d_rsigma[m] = 1.0f/red[0];
        }
        gridbar();
    }
}

__global__ void transpose_scale(const float* __restrict__ W, float* __restrict__ WT, int sidx) {
    __shared__ float tile[32][33];
    const float s = d_rsigma[sidx];
    const int x = blockIdx.x*32 + threadIdx.x, y0 = blockIdx.y*32;
    #pragma unroll
    for (int i = threadIdx.y; i < 32; i += 8)
        tile[i][threadIdx.x] = W[(size_t)(y0+i)*HD + x];
    __syncthreads();
    const int ox = y0 + threadIdx.x, oy0 = blockIdx.x*32;
    #pragma unroll
    for (int i = threadIdx.y; i < 32; i += 8)
        WT[(size_t)(oy0+i)*HD + ox] = tile[threadIdx.x][i] * s;
}

__device__ __forceinline__ void split1(float v, __nv_bfloat16& h, __nv_bfloat16& l) {
    h = __float2bfloat16_rn(v);
    l = __float2bfloat16_rn(v - __bfloat162float(h));
}
__device__ __forceinline__ uint32_t s2u(const void* p) {
    uint32_t a;
    asm("{.reg .u64 t; cvta.to.shared.u64 t, %1; cvt.u32.u64 %0, t;}" : "=r"(a) : "l"(p));
    return a;
}
#define LDSM4(r0,r1,r2,r3,a) asm volatile("ldmatrix.sync.aligned.m8n8.x4.shared.b16 {%0,%1,%2,%3}, [%4];" \
    : "=r"(r0),"=r"(r1),"=r"(r2),"=r"(r3) : "r"(a))
#define MMA(d,a,b0,b1) asm volatile( \
    "mma.sync.aligned.m16n8k16.row.col.f32.bf16.bf16.f32 {%0,%1,%2,%3},{%4,%5,%6,%7},{%8,%9},{%0,%1,%2,%3};" \
    : "+f"(d[0]),"+f"(d[1]),"+f"(d[2]),"+f"(d[3]) \
    : "r"(a[0]),"r"(a[1]),"r"(a[2]),"r"(a[3]),"r"(b0),"r"(b1))

#define STR 40
// D[M,1024] = (A*fa) * ((B*fb))^T (+Add), bf16 3-split. B is [N,K] row-major.
// mode 0: D[r]. mode 1: D at xb scan row. mode 2: D[r] and out2 at hs row.
__global__ void __launch_bounds__(256) mmagemm(const float* __restrict__ A,
    const float* __restrict__ B, float* __restrict__ C, const float* __restrict__ Add,
    int sA, int sB, int mode, int jp, float* __restrict__ out2) {
    __shared__ __nv_bfloat16 sm[4*128*STR];
    __nv_bfloat16 *Ah=sm, *Al=sm+128*STR, *Bh=sm+2*128*STR, *Bl=sm+3*128*STR;
    const int tid=threadIdx.x, lane=tid&31, wid=tid>>5, wm=wid&3, wn=wid>>2;
    const int m0=blockIdx.y*128, n0=blockIdx.x*128;
    const float fa = sA>=0? d_rsigma[sA]:1.f, fb = sB>=0? d_rsigma[sB]:1.f;
    const int lr=tid>>1, lc=(tid&1)*16;
    const float *pa = A + (size_t)(m0+lr)*1024 + lc;
    const float *pb = B + (size_t)(n0+lr)*1024 + lc;
    float4 ra[4], rb[4];
    #pragma unroll
    for (int q=0;q<4;q++){ ra[q]=*(const float4*)(pa+q*4); rb[q]=*(const float4*)(pb+q*4); }
    float acc[2][8][4];
    #pragma unroll
    for (int i=0;i<2;i++)
        #pragma unroll
        for (int j=0;j<8;j++)
            #pragma unroll
            for (int q=0;q<4;q++) acc[i][j][q]=0.f;
    for (int kt=0; kt<32; kt++) {
        #pragma unroll
        for (int q=0;q<4;q++) {
            float va[4]={ra[q].x*fa,ra[q].y*fa,ra[q].z*fa,ra[q].w*fa};
            float vb[4]={rb[q].x*fb,rb[q].y*fb,rb[q].z*fb,rb[q].w*fb};
            #pragma unroll
            for (int e=0;e<4;e++) {
                int col = lc + q*4 + e;
                __nv_bfloat16 h,l;
                split1(va[e],h,l); Ah[lr*STR+col]=h; Al[lr*STR+col]=l;
                split1(vb[e],h,l); Bh[lr*STR+col]=h; Bl[lr*STR+col]=l;
            }
        }
        __syncthreads();
        if (kt<31) {
            pa += 32; pb += 32;
            #pragma unroll
            for (int q=0;q<4;q++){ ra[q]=*(const float4*)(pa+q*4); rb[q]=*(const float4*)(pb+q*4); }
        }
        #pragma unroll
        for (int kh=0;kh<2;kh++) {
            uint32_t ah[2][4], al[2][4];
            #pragma unroll
            for (int ti=0;ti<2;ti++) {
                int aoff = (wm*32+ti*16+(lane&15))*STR + kh*16+(lane>>4)*8;
                uint32_t ad = s2u(Ah+aoff);
                LDSM4(ah[ti][0],ah[ti][1],ah[ti][2],ah[ti][3], ad);
                LDSM4(al[ti][0],al[ti][1],al[ti][2],al[ti][3], ad + 128*STR*2);
            }
            #pragma unroll
            for (int q=0;q<4;q++) {
                int boff = (wn*64+q*16+(lane&7)+((lane>>4)&1)*8)*STR + kh*16+((lane>>3)&1)*8;
                uint32_t bd = s2u(Bh+boff);
                uint32_t h0,h1,h2,h3,l0,l1,l2,l3;
                LDSM4(h0,h1,h2,h3, bd);
                LDSM4(l0,l1,l2,l3, bd + 128*STR*2);
                #pragma unroll
                for (int ti=0;ti<2;ti++) {
                    MMA(acc[ti][q*2],   ah[ti], h0,h1);
                    MMA(acc[ti][q*2],   ah[ti], l0,l1);
                    MMA(acc[ti][q*2],   al[ti], h0,h1);
                    MMA(acc[ti][q*2+1], ah[ti], h2,h3);
                    MMA(acc[ti][q*2+1], ah[ti], l2,l3);
                    MMA(acc[ti][q*2+1], al[ti], h2,h3);
                }
            }
        }
        __syncthreads();
    }
    const int rb0 = m0 + wm*32 + (lane>>2);
    #pragma unroll
    for (int ti=0;ti<2;ti++)
    #pragma unroll
    for (int j=0;j<8;j++)
    #pragma unroll
    for (int hf=0;hf<2;hf++) {
        int r = rb0 + ti*16 + hf*8;
        int c = n0 + wn*64 + j*8 + (lane&3)*2;
        float v0=acc[ti][j][hf*2], v1=acc[ti][j][hf*2+1];
        if (Add) { float2 ad = *(const float2*)(Add+(size_t)r*1024+c); v0+=ad.x; v1+=ad.y; }
        size_t orow=(size_t)r;
        if (mode==1) { int b_=r>>10,t=r&1023,k=t>>4,jj=t&15; orow=(size_t)((((jj<<6)|k)<<5)|b_); }
        *(float2*)(C+orow*1024+c)=make_float2(v0,v1);
        if (mode==2) { int k=r>>5,b_=r&31; size_t o2=(size_t)b_*1024+(size_t)k*16+jp;
                       *(float2*)(out2+o2*1024+c)=make_float2(v0,v1); }
    }
}

__global__ void __launch_bounds__(256) smallgemm(const float* __restrict__ A,
    const float* __restrict__ Q, float* __restrict__ C, const float* __restrict__ Add) {
    __shared__ float As[32*129];
    const int tid = threadIdx.x, row = tid & 31, c0 = blockIdx.x*16 + (tid>>5)*2;
    float acc0 = 0.f, acc1 = 0.f;
    for (int k0 = 0; k0 < 1024; k0 += 128) {
        #pragma unroll
        for (int q = 0; q < 16; q++) {
            int l = q*256 + tid, r = l>>7, cc = l&127;
            As[r*129 + cc] = A[(size_t)r*1024 + k0 + cc];
        }
        __syncthreads();
        #pragma unroll 4
        for (int kk = 0; kk < 128; kk++) {
            float a = As[row*129 + kk];
            float2 qv = *(const float2*)(Q + (size_t)(k0+kk)*1024 + c0);
            acc0 = fmaf(a, qv.x, acc0); acc1 = fmaf(a, qv.y, acc1);
        }
        __syncthreads();
    }
    C[(size_t)row*1024 + c0]   = acc0 + Add[(size_t)row*1024 + c0];
    C[(size_t)row*1024 + c0+1] = acc1 + Add[(size_t)row*1024 + c0 + 1];
}

__global__ void zero32k(float* p) {
    int i = blockIdx.x*256 + threadIdx.x;
    if (i < 32768) p[i] = 0.f;
}

extern "C" void kernel_launch(void* const* d_in, const int* in_sizes, int n_in,
                              void* d_out, int out_size) {
    const float* x  = (const float*)d_in[0];
    const float* WA = (const float*)d_in[1];
    const float* WB = (const float*)d_in[2];
    const float* WC = (const float*)d_in[3];
    float* ys = (float*)d_out;
    float* hs = ys + 33554432UL;
    float* F = nullptr; cudaGetSymbolAddress((void**)&F, g_f);
    float *xb=F+F_XB, *ANT=F+F_ANT, *P1=F+F_P1, *P1T=F+F_P1T,
          *P2=F+F_P2, *P2T=F+F_P2T, *H0=F+F_H0, *H1=F+F_H1, *Cb=F+F_CB;

    spectral_kernel<<<NBS, 256>>>(WA, WB, WC);
    transpose_scale<<<dim3(32,32), dim3(32,8)>>>(WA, ANT, 0);

    // xb = x * (WB/s)^T, scan layout
    mmagemm<<<dim3(8,256),256>>>(x, WB, xb, nullptr, -1, 1, 1, 0, nullptr);
    // Q = (A^16)^T via (P,P^T) squarings
    mmagemm<<<dim3(8,8),256>>>(WA, ANT, P1, nullptr, 0, -1, 0, 0, nullptr);
    mmagemm<<<dim3(8,8),256>>>(ANT, WA, P1T, nullptr, -1, 0, 0, 0, nullptr);
    mmagemm<<<dim3(8,8),256>>>(P1, P1T, P2, nullptr, -1, -1, 0, 0, nullptr);
    mmagemm<<<dim3(8,8),256>>>(P1T, P1, P2T, nullptr, -1, -1, 0, 0, nullptr);
    mmagemm<<<dim3(8,8),256>>>(P2, P2T, P1, nullptr, -1, -1, 0, 0, nullptr);
    mmagemm<<<dim3(8,8),256>>>(P2T, P2, P1T, nullptr, -1, -1, 0, 0, nullptr);
    mmagemm<<<dim3(8,8),256>>>(P1, P1T, P2, nullptr, -1, -1, 0, 0, nullptr);
    mmagemm<<<dim3(8,8),256>>>(P1T, P1, P2T, nullptr, -1, -1, 0, 0, nullptr);
    // pass 1: local scans
    const float* prev = xb;
    for (int j = 1; j < 16; j++) {
        float* dst = (j & 1) ? H1 : H0;
        mmagemm<<<dim3(8,16),256>>>(prev, WA, dst, xb + (size_t)j*2097152UL, -1, 0, 0, 0, nullptr);
        prev = dst;
    }
    // pass 2: carries with Q = P2T
    zero32k<<<128, 256>>>(Cb);
    for (int k = 1; k < 64; k++)
        smallgemm<<<64, 256>>>(Cb + (size_t)(k-1)*32768UL, P2T,
                               Cb + (size_t)k*32768UL, H1 + (size_t)(k-1)*32768UL);
    // pass 3: rescan with true inits, scatter hs
    prev = Cb;
    for (int j = 0; j < 16; j++) {
        float* dst = (j & 1) ? H1 : H0;
        mmagemm<<<dim3(8,16),256>>>(prev, WA, dst, xb + (size_t)j*2097152UL, -1, 0, 2, j, hs);
        prev = dst;
    }
    // ys = hs * (WC/s)^T
    mmagemm<<<dim3(8,256),256>>>(hs, WC, ys, nullptr, -1, 2, 0, 0, nullptr);
    (void)in_sizes; (void)n_in; (void)out_size;
}

// round 7
// speedup vs baseline: 1.4508x; 1.1221x over previous
#include <cuda_runtime.h>
#include <cuda_bf16.h>
#include <cstdint>
#include <math.h>
#define HD 1024
#define NBS 64
// fp32 scratch
#define F_XB 0UL
#define F_QT (F_XB+33554432UL)
#define F_L  (F_QT+1048576UL)
#define F_CB (F_L+2097152UL)
#define F_TOT (F_CB+2097152UL)
__device__ float g_f[F_TOT];
__device__ __nv_bfloat16 g_b[171966464UL];
__device__ float sp_partial[NBS*HD];
__device__ float sp_u[HD], sp_v[HD], sp_w[HD];
__device__ float sp_norm;
__device__ float d_rsigma[3];
__device__ unsigned bar_cnt = 0, bar_gen = 0;

__device__ __forceinline__ void gridbar() {
    __syncthreads(); __threadfence();
    if (threadIdx.x == 0) {
        unsigned g = atomicAdd(&bar_gen, 0u);
        if (atomicAdd(&bar_cnt, 1u) == NBS - 1u) {
            bar_cnt = 0u; __threadfence(); atomicExch(&bar_gen, g + 1u);
        } else while (atomicAdd(&bar_gen, 0u) == g) __nanosleep(64);
    }
    __syncthreads();
}

__global__ void __launch_bounds__(256) spectral_kernel(const float* __restrict__ WA,
    const float* __restrict__ WB, const float* __restrict__ WC) {
    __shared__ float red[256];
    const int tid = threadIdx.x, bid = blockIdx.x, gtid = bid*256 + tid;
    const float* Ws[3] = {WA, WB, WC};
    for (int m = 0; m < 3; m++) {
        const float* W = Ws[m];
        if (gtid < HD) sp_u[gtid] = 0.03125f;
        gridbar();
        for (int it = 0; it <= 10; it++) {
            const int i0 = bid*16;
            float a0=0,a1=0,a2=0,a3=0;
            for (int i = i0; i < i0+16; i++) {
                float ui = __ldcg(&sp_u[i]);
                const float* Wr = W + (size_t)i*HD;
                a0 += Wr[tid]*ui; a1 += Wr[tid+256]*ui;
                a2 += Wr[tid+512]*ui; a3 += Wr[tid+768]*ui;
            }
            sp_partial[bid*HD+tid]=a0; sp_partial[bid*HD+tid+256]=a1;
            sp_partial[bid*HD+tid+512]=a2; sp_partial[bid*HD+tid+768]=a3;
            gridbar();
            if (gtid < HD) { float s=0; for (int b=0;b<NBS;b++) s += __ldcg(&sp_partial[b*HD+gtid]); sp_v[gtid]=s; }
            gridbar();
            if (bid == 0) {
                float s=0;
                #pragma unroll
                for (int q=0;q<4;q++){ float x=__ldcg(&sp_v[tid*4+q]); s+=x*x; }
                red[tid]=s; __syncthreads();
                for (int st=128;st>0;st>>=1){ if(tid<st) red[tid]+=red[tid+st]; __syncthreads(); }
                if (tid==0) sp_norm = sqrtf(red[0]) + 1e-12f;
            }
            gridbar();
            if (gtid < HD) sp_v[gtid] = __ldcg(&sp_v[gtid]) / __ldcg(&sp_norm);
            gridbar();
            if (it == 10) break;
            { const int warp = gtid>>5, lane = gtid&31;
              for (int i = warp; i < HD; i += (NBS*256)/32) {
                const float* Wr = W + (size_t)i*HD;
                float s=0;
                for (int j=lane;j<HD;j+=32) s += Wr[j]*__ldcg(&sp_v[j]);
                #pragma unroll
                for (int o=16;o;o>>=1) s += __shfl_xor_sync(0xffffffffu,s,o);
                if (lane==0) sp_u[i]=s;
              } }
            gridbar();
            if (bid == 0) {
                float s=0;
                #pragma unroll
                for (int q=0;q<4;q++){ float x=__ldcg(&sp_u[tid*4+q]); s+=x*x; }
                red[tid]=s; __syncthreads();
                for (int st=128;st>0;st>>=1){ if(tid<st) red[tid]+=red[tid+st]; __syncthreads(); }
                if (tid==0) sp_norm = sqrtf(red[0]) + 1e-12f;
            }
            gridbar();
            if (gtid < HD) sp_u[gtid] = __ldcg(&sp_u[gtid]) / __ldcg(&sp_norm);
            gridbar();
        }
        { const int warp = gtid>>5, lane = gtid&31;
          for (int i = warp; i < HD; i += (NBS*256)/32) {
            const float* Wr = W + (size_t)i*HD;
            float s=0;
            for (int j=lane;j<HD;j+=32) s += Wr[j]*__ldcg(&sp_v[j]);
            #pragma unroll
            for (int o=16;o;o>>=1) s += __shfl_xor_sync(0xffffffffu,s,o);
            if (lane==0) sp_w[i]=s;
          } }
        gridbar();
        if (bid == 0) {
            float s=0;
            #pragma unroll
            for (int q=0;q<4;q++) s += __ldcg(&sp_u[tid*4+q])*__ldcg(&sp_w[tid*4+q]);
            red[tid]=s; __syncthreads();
            for (int st=128;st>0;st>>=1){ if(tid<st) red[tid]+=red[tid+st]; __syncthreads(); }
            if (tid==0) d_rsigma[m] = 1.0f/red[0];
        }
        gridbar();
    }
}

__device__ __forceinline__ void split1(float v, __nv_bfloat16& h, __nv_bfloat16& l) {
    h = __float2bfloat16_rn(v);
    l = __float2bfloat16_rn(v - __bfloat162float(h));
}
__device__ __forceinline__ uint32_t s2u(const void* p) {
    uint32_t a;
    asm("{.reg .u64 t; cvta.to.shared.u64 t, %1; cvt.u32.u64 %0, t;}" : "=r"(a) : "l"(p));
    return a;
}
#define CP16(d,s) asm volatile("cp.async.cg.shared.global [%0], [%1], 16;" :: "r"(d), "l"(s))
#define CPC() asm volatile("cp.async.commit_group;")
#define CPW1() asm volatile("cp.async.wait_group 1;")
#define CPW0() asm volatile("cp.async.wait_group 0;")
#define LDSM4(r0,r1,r2,r3,a) asm volatile("ldmatrix.sync.aligned.m8n8.x4.shared.b16 {%0,%1,%2,%3}, [%4];" \
    : "=r"(r0),"=r"(r1),"=r"(r2),"=r"(r3) : "r"(a))
#define MMA(d,a,b0,b1) asm volatile( \
    "mma.sync.aligned.m16n8k16.row.col.f32.bf16.bf16.f32 {%0,%1,%2,%3},{%4,%5,%6,%7},{%8,%9},{%0,%1,%2,%3};" \
    : "+f"(d[0]),"+f"(d[1]),"+f"(d[2]),"+f"(d[3]) \
    : "r"(a[0]),"r"(a[1]),"r"(a[2]),"r"(a[3]),"r"(b0),"r"(b1))

// split kernel: oh/ol = split(src * rsigma[sidx]); 4 elems/thread
__global__ void splitk(const float* __restrict__ src, __nv_bfloat16* __restrict__ oh,
                       __nv_bfloat16* __restrict__ ol, int sidx) {
    float f = sidx >= 0 ? d_rsigma[sidx] : 1.f;
    size_t i = ((size_t)blockIdx.x*256 + threadIdx.x)*4;
    float4 v = *(const float4*)(src + i);
    __nv_bfloat16 h0,l0,h1,l1,h2,l2,h3,l3;
    split1(v.x*f,h0,l0); split1(v.y*f,h1,l1); split1(v.z*f,h2,l2); split1(v.w*f,h3,l3);
    __nv_bfloat162 a,b;
    a.x=h0;a.y=h1;b.x=h2;b.y=h3;
    *(__nv_bfloat162*)(oh+i)=a; *(__nv_bfloat162*)(oh+i+2)=b;
    a.x=l0;a.y=l1;b.x=l2;b.y=l3;
    *(__nv_bfloat162*)(ol+i)=a; *(__nv_bfloat162*)(ol+i+2)=b;
}

// transpose + scale + split
__global__ void tsplit(const float* __restrict__ W, __nv_bfloat16* __restrict__ oh,
                       __nv_bfloat16* __restrict__ ol, int sidx) {
    __shared__ float t[32][33];
    float s = d_rsigma[sidx];
    int x = blockIdx.x*32 + threadIdx.x, y0 = blockIdx.y*32;
    #pragma unroll
    for (int i = threadIdx.y; i < 32; i += 8)
        t[i][threadIdx.x] = W[(size_t)(y0+i)*HD + x];
    __syncthreads();
    int ox = y0 + threadIdx.x, oy0 = blockIdx.x*32;
    #pragma unroll
    for (int i = threadIdx.y; i < 32; i += 8) {
        __nv_bfloat16 h,l; split1(t[threadIdx.x][i]*s,h,l);
        oh[(size_t)(oy0+i)*HD + ox] = h;
        ol[(size_t)(oy0+i)*HD + ox] = l;
    }
}

#define STR 40
// D[M,1024]=(Ah+Al)*((Bh+Bl))^T (+Add) via 3-term bf16 MMA, cp.async double-buffered.
// mode 0: Cf?/Oh? at row r. mode 1: Cf at xb scan row; Oh/Ol if scan row<2048.
// mode 2: Oh/Ol at r; Cf+O2h/O2l at hs row.
__global__ void __launch_bounds__(256,2) mmagemm(
    const __nv_bfloat16* __restrict__ Ahh, const __nv_bfloat16* __restrict__ All,
    const __nv_bfloat16* __restrict__ Bhh, const __nv_bfloat16* __restrict__ Bll,
    const float* __restrict__ Add, float* __restrict__ Cf,
    __nv_bfloat16* __restrict__ Oh, __nv_bfloat16* __restrict__ Ol,
    __nv_bfloat16* __restrict__ O2h, __nv_bfloat16* __restrict__ O2l,
    int mode, int jp)
{
    extern __shared__ __nv_bfloat16 smx[];
    const int tid=threadIdx.x, lane=tid&31, wid=tid>>5, wm=wid&3, wn=wid>>2;
    const int m0=blockIdx.y*128, n0=blockIdx.x*128;
    const int lr=tid>>1, lc=(tid&1)*16;
    const uint32_t sb=s2u(smx);
    const __nv_bfloat16* srcs[4]={Ahh,All,Bhh,Bll};
    float acc[2][8][4];
    #pragma unroll
    for (int i=0;i<2;i++)
        #pragma unroll
        for (int j=0;j<8;j++)
            #pragma unroll
            for (int q=0;q<4;q++) acc[i][j][q]=0.f;
    auto ldst = [&](int kt, int st){
        const int k0 = kt*32;
        #pragma unroll
        for (int a=0;a<4;a++) {
            int row = (a<2 ? m0 : n0) + lr;
            const char* s = (const char*)(srcs[a] + (size_t)row*1024 + k0 + lc);
            uint32_t d = sb + (uint32_t)(st*40960 + a*10240 + (lr*STR+lc)*2);
            CP16(d, s); CP16(d+16, s+16);
        }
    };
    ldst(0,0); CPC();
    for (int kt=0; kt<32; kt++) {
        if (kt<31) { ldst(kt+1,(kt+1)&1); CPC(); CPW1(); } else CPW0();
        __syncthreads();
        const uint32_t ab = sb + (kt&1)*40960;
        #pragma unroll
        for (int kh=0;kh<2;kh++) {
            uint32_t ah[2][4], al[2][4];
            #pragma unroll
            for (int ti=0;ti<2;ti++) {
                uint32_t ad = ab + (uint32_t)(((wm*32+ti*16+(lane&15))*STR + kh*16+(lane>>4)*8)*2);
                LDSM4(ah[ti][0],ah[ti][1],ah[ti][2],ah[ti][3], ad);
                LDSM4(al[ti][0],al[ti][1],al[ti][2],al[ti][3], ad+10240);
            }
            #pragma unroll
            for (int q=0;q<4;q++) {
                uint32_t bd = ab + 20480u + (uint32_t)(((wn*64+q*16+(lane&7)+((lane>>4)&1)*8)*STR + kh*16+((lane>>3)&1)*8)*2);
                uint32_t h0,h1,h2,h3,l0,l1,l2,l3;
                LDSM4(h0,h1,h2,h3, bd);
                LDSM4(l0,l1,l2,l3, bd+10240);
                #pragma unroll
                for (int ti=0;ti<2;ti++) {
                    MMA(acc[ti][q*2],   ah[ti], h0,h1);
                    MMA(acc[ti][q*2],   ah[ti], l0,l1);
                    MMA(acc[ti][q*2],   al[ti], h0,h1);
                    MMA(acc[ti][q*2+1], ah[ti], h2,h3);
                    MMA(acc[ti][q*2+1], ah[ti], l2,l3);
                    MMA(acc[ti][q*2+1], al[ti], h2,h3);
                }
            }
        }
        __syncthreads();
    }
    const int rb0 = m0 + wm*32 + (lane>>2);
    #pragma unroll
    for (int ti=0;ti<2;ti++)
    #pragma unroll
    for (int j=0;j<8;j++)
    #pragma unroll
    for (int hf=0;hf<2;hf++) {
        int r = rb0 + ti*16 + hf*8;
        int c = n0 + wn*64 + j*8 + (lane&3)*2;
        float v0=acc[ti][j][hf*2], v1=acc[ti][j][hf*2+1];
        if (Add) { float2 ad = *(const float2*)(Add+(size_t)r*1024+c); v0+=ad.x; v1+=ad.y; }
        __nv_bfloat16 h0,l0,h1,l1; split1(v0,h0,l0); split1(v1,h1,l1);
        __nv_bfloat162 ph,pl; ph.x=h0; ph.y=h1; pl.x=l0; pl.y=l1;
        if (mode==2) {
            *(__nv_bfloat162*)(Oh+(size_t)r*1024+c)=ph;
            *(__nv_bfloat162*)(Ol+(size_t)r*1024+c)=pl;
            int k=r>>5, b_=r&31;
            size_t o2=(size_t)b_*1024+(size_t)k*16+jp;
            *(float2*)(Cf+o2*1024+c)=make_float2(v0,v1);
            *(__nv_bfloat162*)(O2h+o2*1024+c)=ph;
            *(__nv_bfloat162*)(O2l+o2*1024+c)=pl;
        } else {
            size_t orow=(size_t)r;
            if (mode==1) { int b_=r>>10,t=r&1023,k=t>>4,jj=t&15; orow=(size_t)((((jj<<6)|k)<<5)|b_); }
            if (Cf) *(float2*)(Cf+orow*1024+c)=make_float2(v0,v1);
            if (Oh && (mode!=1 || orow<2048)) {
                *(__nv_bfloat162*)(Oh+orow*1024+c)=ph;
                *(__nv_bfloat162*)(Ol+orow*1024+c)=pl;
            }
        }
    }
}

// fp32 carry GEMM: C[32,1024] = A*Q + Add, plus bf16 split out
__global__ void __launch_bounds__(256) smallgemm(const float* __restrict__ A,
    const float* __restrict__ Q, float* __restrict__ C, const float* __restrict__ Add,
    __nv_bfloat16* __restrict__ Ch, __nv_bfloat16* __restrict__ Cl) {
    __shared__ float As[32*129];
    const int tid = threadIdx.x, row = tid & 31, c0 = blockIdx.x*16 + (tid>>5)*2;
    float acc0 = 0.f, acc1 = 0.f;
    for (int k0 = 0; k0 < 1024; k0 += 128) {
        #pragma unroll
        for (int q = 0; q < 16; q++) {
            int l = q*256 + tid, r = l>>7, cc = l&127;
            As[r*129 + cc] = A[(size_t)r*1024 + k0 + cc];
        }
        __syncthreads();
        #pragma unroll 4
        for (int kk = 0; kk < 128; kk++) {
            float a = As[row*129 + kk];
            float2 qv = *(const float2*)(Q + (size_t)(k0+kk)*1024 + c0);
            acc0 = fmaf(a, qv.x, acc0); acc1 = fmaf(a, qv.y, acc1);
        }
        __syncthreads();
    }
    float r0 = acc0 + Add[(size_t)row*1024 + c0];
    float r1 = acc1 + Add[(size_t)row*1024 + c0 + 1];
    C[(size_t)row*1024 + c0]   = r0;
    C[(size_t)row*1024 + c0+1] = r1;
    __nv_bfloat16 h,l;
    split1(r0,h,l); Ch[(size_t)row*1024+c0]=h;   Cl[(size_t)row*1024+c0]=l;
    split1(r1,h,l); Ch[(size_t)row*1024+c0+1]=h; Cl[(size_t)row*1024+c0+1]=l;
}

__global__ void zero_cb(float* c, __nv_bfloat16* ch, __nv_bfloat16* cl) {
    int i = blockIdx.x*256 + threadIdx.x;
    if (i < 32768) { c[i]=0.f; ch[i]=__float2bfloat16(0.f); cl[i]=__float2bfloat16(0.f); }
}

extern "C" void kernel_launch(void* const* d_in, const int* in_sizes, int n_in,
                              void* d_out, int out_size) {
    const float* x  = (const float*)d_in[0];
    const float* WA = (const float*)d_in[1];
    const float* WB = (const float*)d_in[2];
    const float* WC = (const float*)d_in[3];
    float* ys = (float*)d_out;
    float* hs = ys + 33554432UL;
    float* F = nullptr; cudaGetSymbolAddress((void**)&F, g_f);
    __nv_bfloat16* G = nullptr; cudaGetSymbolAddress((void**)&G, g_b);
    float *xb=F+F_XB, *QT=F+F_QT, *L=F+F_L, *Cb=F+F_CB;
    __nv_bfloat16* p = G;
    #define NXT(nm,sz) __nv_bfloat16 *nm##h=p, *nm##l=p+(sz); p += 2UL*(sz);
    NXT(X,33554432UL) NXT(WA_,1048576UL) NXT(WAT,1048576UL) NXT(WB_,1048576UL)
    NXT(WC_,1048576UL) NXT(P1,1048576UL) NXT(P1T,1048576UL) NXT(P2,1048576UL)
    NXT(P2T,1048576UL) NXT(P3,1048576UL) NXT(P3T,1048576UL)
    NXT(XB0,2097152UL) NXT(S0,2097152UL) NXT(S1,2097152UL) NXT(CB,2097152UL)
    NXT(HS,33554432UL)
    #undef NXT

    cudaFuncSetAttribute(mmagemm, cudaFuncAttributeMaxDynamicSharedMemorySize, 81920);

    spectral_kernel<<<NBS, 256>>>(WA, WB, WC);
    splitk<<<32768,256>>>(x, Xh, Xl, -1);
    splitk<<<1024,256>>>(WA, WA_h, WA_l, 0);
    splitk<<<1024,256>>>(WB, WB_h, WB_l, 1);
    splitk<<<1024,256>>>(WC, WC_h, WC_l, 2);
    tsplit<<<dim3(32,32), dim3(32,8)>>>(WA, WATh, WATl, 0);

    // xb = x*(WB/s)^T (scan layout) + chunk-0 bf16 slice
    mmagemm<<<dim3(8,256),256,81920>>>(Xh,Xl, WB_h,WB_l, nullptr, xb, XB0h,XB0l, nullptr,nullptr, 1,0);
    // squaring chain to (A^16)^T fp32
    mmagemm<<<dim3(8,8),256,81920>>>(WA_h,WA_l, WATh,WATl, nullptr,nullptr, P1h,P1l, nullptr,nullptr,0,0);
    mmagemm<<<dim3(8,8),256,81920>>>(WATh,WATl, WA_h,WA_l, nullptr,nullptr, P1Th,P1Tl, nullptr,nullptr,0,0);
    mmagemm<<<dim3(8,8),256,81920>>>(P1h,P1l, P1Th,P1Tl, nullptr,nullptr, P2h,P2l, nullptr,nullptr,0,0);
    mmagemm<<<dim3(8,8),256,81920>>>(P1Th,P1Tl, P1h,P1l, nullptr,nullptr, P2Th,P2Tl, nullptr,nullptr,0,0);
    mmagemm<<<dim3(8,8),256,81920>>>(P2h,P2l, P2Th,P2Tl, nullptr,nullptr, P3h,P3l, nullptr,nullptr,0,0);
    mmagemm<<<dim3(8,8),256,81920>>>(P2Th,P2Tl, P2h,P2l, nullptr,nullptr, P3Th,P3Tl, nullptr,nullptr,0,0);
    mmagemm<<<dim3(8,8),256,81920>>>(P3Th,P3Tl, P3h,P3l, nullptr, QT, nullptr,nullptr, nullptr,nullptr,0,0);
    // pass 1: local scans, bf16 state chain; last step also fp32 -> L
    __nv_bfloat16 *ph_=XB0h, *pl_=XB0l;
    for (int j = 1; j < 16; j++) {
        __nv_bfloat16 *dh = (j&1)?S1h:S0h, *dl = (j&1)?S1l:S0l;
        mmagemm<<<dim3(8,16),256,81920>>>(ph_,pl_, WA_h,WA_l, xb+(size_t)j*2097152UL,
            (j==15)?L:nullptr, dh,dl, nullptr,nullptr, 0,0);
        ph_=dh; pl_=dl;
    }
    // pass 2: carries
    zero_cb<<<128,256>>>(Cb, CBh, CBl);
    for (int k = 1; k < 64; k++)
        smallgemm<<<64,256>>>(Cb+(size_t)(k-1)*32768UL, QT, Cb+(size_t)k*32768UL,
            L+(size_t)(k-1)*32768UL, CBh+(size_t)k*32768UL, CBl+(size_t)k*32768UL);
    // pass 3: rescan with true inits; hs fp32 + HS bf16
    ph_=CBh; pl_=CBl;
    for (int j = 0; j < 16; j++) {
        __nv_bfloat16 *dh = (j&1)?S1h:S0h, *dl = (j&1)?S1l:S0l;
        mmagemm<<<dim3(8,16),256,81920>>>(ph_,pl_, WA_h,WA_l, xb+(size_t)j*2097152UL,
            hs, dh,dl, HSh,HSl, 2,j);
        ph_=dh; pl_=dl;
    }
    // ys = hs*(WC/s)^T
    mmagemm<<<dim3(8,256),256,81920>>>(HSh,HSl, WC_h,WC_l, nullptr, ys, nullptr,nullptr, nullptr,nullptr, 0,0);
    (void)in_sizes; (void)n_in; (void)out_size;
}